// round 7
// baseline (speedup 1.0000x reference)
#include <cuda_runtime.h>

// out[b, f, s] = x[b, 0, s] * w[f, s] + bias[f, s]
// B=128, F=256, S=4096. HBM-write-bound: 512 MiB out.
//
// R7: each CTA owns a CONTIGUOUS 512 KB output slice: one batch b x 32
// consecutive filters x full S row. x[b] row fully register-cached
// (4 float4/thread = 16 regs, reused 32x); w/bias streamed once per filter.
// The CTA store stream is a single monotone linear 512 KB sweep — zero
// stride hops (R5 hopped every 4 KB).

#define S4     1024        // float4 per row (4096 floats)
#define NFILT  256
#define BATCH  128
#define FT     32          // filters per CTA
#define NCHUNK 4           // 4 chunks x 256 threads x float4 = 1024 float4 row

__global__ __launch_bounds__(256, 2) void dense_filter_expand_kernel(
    const float4* __restrict__ x,     // [B, S4]
    const float4* __restrict__ w,     // [F, S4]
    const float4* __restrict__ bias,  // [F, S4]
    float4* __restrict__ out)         // [B, F, S4]
{
    const int t  = threadIdx.x;                // 0..255
    const int fg = blockIdx.x;                 // 0..7   filter group
    const int b  = blockIdx.y;                 // 0..127 batch
    const int f0 = fg * FT;

    // Register-cache the entire x[b] row: 4 float4 per thread (16 regs).
    float4 xv[NCHUNK];
    {
        const float4* xr = x + (size_t)b * S4;
#pragma unroll
        for (int i = 0; i < NCHUNK; i++)
            xv[i] = __ldg(&xr[t + i * 256]);
    }

#pragma unroll 1
    for (int ff = 0; ff < FT; ff++) {
        const int f = f0 + ff;
        const float4* wr = w    + (size_t)f * S4;
        const float4* br = bias + (size_t)f * S4;
        float4* orow = out + ((size_t)b * NFILT + f) * S4;

        // Stream the filter row once: load 4+4 chunks, fma, 4 linear stores.
        float4 wv[NCHUNK], bv[NCHUNK];
#pragma unroll
        for (int i = 0; i < NCHUNK; i++) {
            wv[i] = __ldg(&wr[t + i * 256]);
            bv[i] = __ldg(&br[t + i * 256]);
        }
#pragma unroll
        for (int i = 0; i < NCHUNK; i++) {
            float4 o;
            o.x = fmaf(xv[i].x, wv[i].x, bv[i].x);
            o.y = fmaf(xv[i].y, wv[i].y, bv[i].y);
            o.z = fmaf(xv[i].z, wv[i].z, bv[i].z);
            o.w = fmaf(xv[i].w, wv[i].w, bv[i].w);
            // Streaming store: output is write-once, never re-read.
            __stcs(&orow[t + i * 256], o);
        }
    }
}

extern "C" void kernel_launch(void* const* d_in, const int* in_sizes, int n_in,
                              void* d_out, int out_size) {
    const float4* x    = (const float4*)d_in[0];   // inputs [128,1,4096]
    const float4* w    = (const float4*)d_in[1];   // w [256,4096]
    const float4* bias = (const float4*)d_in[2];   // b [256,4096]
    float4* out = (float4*)d_out;

    dim3 grid(NFILT / FT, BATCH);                  // (8, 128) = 1024
    dense_filter_expand_kernel<<<grid, 256>>>(x, w, bias, out);
}

// round 8
// speedup vs baseline: 1.2051x; 1.2051x over previous
#include <cuda_runtime.h>

// out[b, f, s] = x[b, 0, s] * w[f, s] + bias[f, s]
// B=128, F=256, S=4096. HBM-write-bound: 512 MiB out.
//
// R8: R5 structure (FT=8 filters reg-cached, filter-inner 16KB-stride store
// bursts, __stcs) but x tile staged in SHARED MEMORY in the preamble.
// Steady loop = 1 LDS (29 cyc) + 8 STG.128 — no dependent global loads.
// (R5's loop paid a ~250-cyc L2-hit stall per batch iteration.)

#define S4     1024        // float4 per row (4096 floats)
#define NFILT  256
#define BATCH  128
#define FT     8           // filters per block (w/bias register-cached)
#define BT     8           // batches per block (x staged in smem)
#define CHUNK4 256         // float4 per s-chunk, one per thread

__global__ __launch_bounds__(256, 2) void dense_filter_expand_kernel(
    const float4* __restrict__ x,     // [B, S4]
    const float4* __restrict__ w,     // [F, S4]
    const float4* __restrict__ bias,  // [F, S4]
    float4* __restrict__ out)         // [B, F, S4]
{
    __shared__ float4 xs[BT * CHUNK4];         // 32 KB

    const int t  = threadIdx.x;                // 0..255
    const int sc = blockIdx.x;                 // 0..3   s-chunk
    const int fg = blockIdx.y;                 // 0..31  filter group
    const int bg = blockIdx.z;                 // 0..15  batch group
    const int s4 = sc * CHUNK4 + t;            // float4 index within a row
    const int b0 = bg * BT;
    const int f0 = fg * FT;

    // Preamble: stage x chunks for 8 batches into smem (8 independent LDGs).
#pragma unroll
    for (int i = 0; i < BT; i++)
        xs[i * CHUNK4 + t] = __ldg(&x[(size_t)(b0 + i) * S4 + s4]);

    // Register-cache w/bias chunks for the 8 filters (64 regs, full MLP).
    float4 wv[FT], bv[FT];
#pragma unroll
    for (int ff = 0; ff < FT; ff++) {
        wv[ff] = __ldg(&w[(size_t)(f0 + ff) * S4 + s4]);
        bv[ff] = __ldg(&bias[(size_t)(f0 + ff) * S4 + s4]);
    }
    __syncthreads();

    // Steady state: 1 LDS + 8 streaming stores per batch. Zero global loads.
#pragma unroll 1
    for (int bb = 0; bb < BT; bb++) {
        const float4 xv = xs[bb * CHUNK4 + t];

        float4* obase = out + ((size_t)(b0 + bb) * NFILT + f0) * S4 + s4;
#pragma unroll
        for (int ff = 0; ff < FT; ff++) {
            float4 o;
            o.x = fmaf(xv.x, wv[ff].x, bv[ff].x);
            o.y = fmaf(xv.y, wv[ff].y, bv[ff].y);
            o.z = fmaf(xv.z, wv[ff].z, bv[ff].z);
            o.w = fmaf(xv.w, wv[ff].w, bv[ff].w);
            // Streaming store: output is write-once, never re-read.
            __stcs(obase + (size_t)ff * S4, o);
        }
    }
}

extern "C" void kernel_launch(void* const* d_in, const int* in_sizes, int n_in,
                              void* d_out, int out_size) {
    const float4* x    = (const float4*)d_in[0];   // inputs [128,1,4096]
    const float4* w    = (const float4*)d_in[1];   // w [256,4096]
    const float4* bias = (const float4*)d_in[2];   // b [256,4096]
    float4* out = (float4*)d_out;

    dim3 grid(S4 / CHUNK4, NFILT / FT, BATCH / BT);  // (4, 32, 16) = 2048
    dense_filter_expand_kernel<<<grid, 256>>>(x, w, bias, out);
}